// round 1
// baseline (speedup 1.0000x reference)
#include <cuda_runtime.h>
#include <cuda_bf16.h>
#include <math.h>

// Problem constants
#define BATCH 8
#define SEQ   2048
#define DMODEL 512

// Tiling config for fp32 GEMM
#define BM 128
#define BN 128
#define BK 8
#define TM 8
#define TN 8
#define NTHREADS 256

// Scratch for Q, K, V projections: [B*N, D] each (32 MB each)
__device__ float g_Q[BATCH * SEQ * DMODEL];
__device__ float g_K[BATCH * SEQ * DMODEL];
__device__ float g_V[BATCH * SEQ * DMODEL];

// ---------------------------------------------------------------------------
// C[M,Ncols] = A[M,K] @ B[K,Ncols] (+ bias[n]), row-major, batched via blockIdx.z
// Requires M % BM == 0, Ncols % BN == 0, K % BK == 0.
// ---------------------------------------------------------------------------
__global__ __launch_bounds__(NTHREADS, 2)
void gemm_nn(const float* __restrict__ A, const float* __restrict__ B,
             const float* __restrict__ bias, float* __restrict__ C,
             int M, int Ncols, int K,
             long strideA, long strideB, long strideC)
{
    const long bz = blockIdx.z;
    A += bz * strideA;
    B += bz * strideB;
    C += bz * strideC;

    __shared__ float As[BK][BM + 4];
    __shared__ float Bs[BK][BN + 4];

    const int tid = threadIdx.x;
    const int bm = blockIdx.y * BM;
    const int bn = blockIdx.x * BN;

    // A-tile load mapping: 128 rows x 8 cols, one float4 per thread
    const int arow = tid >> 1;            // 0..127
    const int acol = (tid & 1) * 4;       // 0 or 4
    // B-tile load mapping: 8 rows x 128 cols, one float4 per thread
    const int brow = tid >> 5;            // 0..7
    const int bcol = (tid & 31) * 4;      // 0..124

    const int tx = tid & 15;              // col group
    const int ty = tid >> 4;              // row group

    float acc[TM][TN] = {};

    for (int k0 = 0; k0 < K; k0 += BK) {
        float4 av = *(const float4*)(A + (long)(bm + arow) * K + (k0 + acol));
        As[acol + 0][arow] = av.x;
        As[acol + 1][arow] = av.y;
        As[acol + 2][arow] = av.z;
        As[acol + 3][arow] = av.w;

        float4 bv = *(const float4*)(B + (long)(k0 + brow) * Ncols + (bn + bcol));
        *(float4*)&Bs[brow][bcol] = bv;

        __syncthreads();

        #pragma unroll
        for (int k = 0; k < BK; k++) {
            float ar[TM], br[TN];
            #pragma unroll
            for (int i = 0; i < TM; i++) ar[i] = As[k][ty * TM + i];
            #pragma unroll
            for (int j = 0; j < TN; j++) br[j] = Bs[k][tx * TN + j];
            #pragma unroll
            for (int i = 0; i < TM; i++)
                #pragma unroll
                for (int j = 0; j < TN; j++)
                    acc[i][j] = fmaf(ar[i], br[j], acc[i][j]);
        }
        __syncthreads();
    }

    #pragma unroll
    for (int i = 0; i < TM; i++) {
        const long row = bm + ty * TM + i;
        #pragma unroll
        for (int j = 0; j < TN; j += 4) {
            const int col = bn + tx * TN + j;
            float4 v;
            v.x = acc[i][j + 0];
            v.y = acc[i][j + 1];
            v.z = acc[i][j + 2];
            v.w = acc[i][j + 3];
            if (bias) {
                v.x += bias[col + 0];
                v.y += bias[col + 1];
                v.z += bias[col + 2];
                v.w += bias[col + 3];
            }
            *(float4*)(C + row * Ncols + col) = v;
        }
    }
}

// ---------------------------------------------------------------------------
// C[M,Ncols] = alpha * A[M,K] @ B[Ncols,K]^T  (both K-major), batched.
// Used for scores = scale * Q @ K^T.
// ---------------------------------------------------------------------------
__global__ __launch_bounds__(NTHREADS, 2)
void gemm_nt(const float* __restrict__ A, const float* __restrict__ B,
             float* __restrict__ C,
             int M, int Ncols, int K, float alpha,
             long strideA, long strideB, long strideC)
{
    const long bz = blockIdx.z;
    A += bz * strideA;
    B += bz * strideB;
    C += bz * strideC;

    __shared__ float As[BK][BM + 4];
    __shared__ float Bs[BK][BN + 4];

    const int tid = threadIdx.x;
    const int bm = blockIdx.y * BM;
    const int bn = blockIdx.x * BN;

    const int arow = tid >> 1;
    const int acol = (tid & 1) * 4;

    const int tx = tid & 15;
    const int ty = tid >> 4;

    float acc[TM][TN] = {};

    for (int k0 = 0; k0 < K; k0 += BK) {
        float4 av = *(const float4*)(A + (long)(bm + arow) * K + (k0 + acol));
        As[acol + 0][arow] = av.x;
        As[acol + 1][arow] = av.y;
        As[acol + 2][arow] = av.z;
        As[acol + 3][arow] = av.w;

        // B tile: rows are n (128 of them), cols are k (8) -> store transposed
        float4 bv = *(const float4*)(B + (long)(bn + arow) * K + (k0 + acol));
        Bs[acol + 0][arow] = bv.x;
        Bs[acol + 1][arow] = bv.y;
        Bs[acol + 2][arow] = bv.z;
        Bs[acol + 3][arow] = bv.w;

        __syncthreads();

        #pragma unroll
        for (int k = 0; k < BK; k++) {
            float ar[TM], br[TN];
            #pragma unroll
            for (int i = 0; i < TM; i++) ar[i] = As[k][ty * TM + i];
            #pragma unroll
            for (int j = 0; j < TN; j++) br[j] = Bs[k][tx * TN + j];
            #pragma unroll
            for (int i = 0; i < TM; i++)
                #pragma unroll
                for (int j = 0; j < TN; j++)
                    acc[i][j] = fmaf(ar[i], br[j], acc[i][j]);
        }
        __syncthreads();
    }

    #pragma unroll
    for (int i = 0; i < TM; i++) {
        const long row = bm + ty * TM + i;
        #pragma unroll
        for (int j = 0; j < TN; j += 4) {
            const int col = bn + tx * TN + j;
            float4 v;
            v.x = acc[i][j + 0] * alpha;
            v.y = acc[i][j + 1] * alpha;
            v.z = acc[i][j + 2] * alpha;
            v.w = acc[i][j + 3] * alpha;
            *(float4*)(C + row * Ncols + col) = v;
        }
    }
}

// ---------------------------------------------------------------------------
// In-place softmax over axis 1 (the QUERY axis i) of S[b, i, j].
// Each thread owns one column j of one batch; global accesses are coalesced
// (consecutive threads -> consecutive j).
// ---------------------------------------------------------------------------
__global__ void softmax_axis1(float* __restrict__ S)
{
    const int j = blockIdx.x * blockDim.x + threadIdx.x;  // 0..SEQ-1
    const long b = blockIdx.y;
    float* base = S + b * (long)SEQ * SEQ + j;

    // Pass 1: online max + sum
    float m = -INFINITY, s = 0.0f;
    for (int i = 0; i < SEQ; i++) {
        float x = base[(long)i * SEQ];
        float nm = fmaxf(m, x);
        s = s * __expf(m - nm) + __expf(x - nm);
        m = nm;
    }
    const float inv = 1.0f / s;

    // Pass 2: normalize
    for (int i = 0; i < SEQ; i++) {
        float x = base[(long)i * SEQ];
        base[(long)i * SEQ] = __expf(x - m) * inv;
    }
}

// ---------------------------------------------------------------------------
// kernel_launch
// ---------------------------------------------------------------------------
extern "C" void kernel_launch(void* const* d_in, const int* in_sizes, int n_in,
                              void* d_out, int out_size)
{
    const float* x  = (const float*)d_in[0];  // [B, N, D]
    const float* Wq = (const float*)d_in[1];  // [D, D]
    const float* bq = (const float*)d_in[2];  // [D]
    const float* Wk = (const float*)d_in[3];
    const float* bk = (const float*)d_in[4];
    const float* Wv = (const float*)d_in[5];
    const float* bv = (const float*)d_in[6];

    float* out     = (float*)d_out;                           // [B, N, D]
    float* weights = out + (long)BATCH * SEQ * DMODEL;        // [B, N, N]

    float* Q; cudaGetSymbolAddress((void**)&Q, g_Q);
    float* K; cudaGetSymbolAddress((void**)&K, g_K);
    float* V; cudaGetSymbolAddress((void**)&V, g_V);

    const dim3 blk(NTHREADS);

    // 1) QKV projections: [16384, 512] = [16384, 512] @ [512, 512] + bias
    {
        dim3 grid(DMODEL / BN, (BATCH * SEQ) / BM, 1);
        gemm_nn<<<grid, blk>>>(x, Wq, bq, Q, BATCH * SEQ, DMODEL, DMODEL, 0, 0, 0);
        gemm_nn<<<grid, blk>>>(x, Wk, bk, K, BATCH * SEQ, DMODEL, DMODEL, 0, 0, 0);
        gemm_nn<<<grid, blk>>>(x, Wv, bv, V, BATCH * SEQ, DMODEL, DMODEL, 0, 0, 0);
    }

    // 2) scores = scale * Q @ K^T  per batch, written straight into weights region
    {
        const float scale = 1.0f / sqrtf((float)DMODEL);
        dim3 grid(SEQ / BN, SEQ / BM, BATCH);
        gemm_nt<<<grid, blk>>>(Q, K, weights, SEQ, SEQ, DMODEL, scale,
                               (long)SEQ * DMODEL, (long)SEQ * DMODEL,
                               (long)SEQ * SEQ);
    }

    // 3) softmax over axis 1 (queries), in place
    {
        dim3 grid(SEQ / 256, BATCH);
        softmax_axis1<<<grid, dim3(256)>>>(weights);
    }

    // 4) out = weights @ V  per batch
    {
        dim3 grid(DMODEL / BN, SEQ / BM, BATCH);
        gemm_nn<<<grid, blk>>>(weights, V, nullptr, out, SEQ, DMODEL, SEQ,
                               (long)SEQ * SEQ, (long)SEQ * DMODEL,
                               (long)SEQ * DMODEL);
    }
}

// round 5
// speedup vs baseline: 2.1712x; 2.1712x over previous
#include <cuda_runtime.h>
#include <cuda_bf16.h>
#include <math.h>
#include <stdint.h>

// Problem constants
#define BATCH 8
#define SEQ   2048
#define DMODEL 512

#define BM 128
#define BN 128
#define BKF 32          // fp32 k per chunk
#define LDK 40          // padded bf16 row stride (32 + 8)

// Scratch for Q, K, V projections: [B*N, D] each (32 MB each)
__device__ float g_Q[BATCH * SEQ * DMODEL];
__device__ float g_K[BATCH * SEQ * DMODEL];
__device__ float g_V[BATCH * SEQ * DMODEL];

// ===========================================================================
// PTX helpers
// ===========================================================================
__device__ __forceinline__ uint32_t smem_u32(const void* p) {
    uint32_t a;
    asm("{ .reg .u64 t; cvta.to.shared.u64 t, %1; cvt.u32.u64 %0, t; }"
        : "=r"(a) : "l"(p));
    return a;
}

__device__ __forceinline__ void ldm_x4(uint32_t* r, uint32_t addr) {
    asm volatile("ldmatrix.sync.aligned.m8n8.x4.shared.b16 {%0,%1,%2,%3}, [%4];"
        : "=r"(r[0]), "=r"(r[1]), "=r"(r[2]), "=r"(r[3]) : "r"(addr));
}
__device__ __forceinline__ void ldm_x2(uint32_t* r, uint32_t addr) {
    asm volatile("ldmatrix.sync.aligned.m8n8.x2.shared.b16 {%0,%1}, [%2];"
        : "=r"(r[0]), "=r"(r[1]) : "r"(addr));
}

__device__ __forceinline__ void mma16816(float* c, const uint32_t* a, const uint32_t* b) {
    asm volatile(
        "mma.sync.aligned.m16n8k16.row.col.f32.bf16.bf16.f32 "
        "{%0,%1,%2,%3}, {%4,%5,%6,%7}, {%8,%9}, {%0,%1,%2,%3};"
        : "+f"(c[0]), "+f"(c[1]), "+f"(c[2]), "+f"(c[3])
        : "r"(a[0]), "r"(a[1]), "r"(a[2]), "r"(a[3]), "r"(b[0]), "r"(b[1]));
}

// ===========================================================================
// Tile loaders: fp32 gmem -> split bf16 (hi/lo) in padded [row][k] smem.
// Tile = 128 rows x 32 k.
// ===========================================================================

// Direct: rows are tile rows, src points at [row0][k0], leading dim ld.
__device__ __forceinline__ void load_direct(
    const float* __restrict__ src, int ld,
    __nv_bfloat16* __restrict__ hi, __nv_bfloat16* __restrict__ lo, int t)
{
    const int kq = (t & 3) * 4;     // 0,4,8,12
    const int r0 = t >> 2;          // 0..63
    #pragma unroll
    for (int rb = 0; rb < 2; rb++) {
        const int r = r0 + rb * 64;
        #pragma unroll
        for (int i = 0; i < 2; i++) {
            const int k = kq + i * 16;
            float4 a = *(const float4*)(src + (long)r * ld + k);
            __nv_bfloat162 h0 = __floats2bfloat162_rn(a.x, a.y);
            __nv_bfloat162 h1 = __floats2bfloat162_rn(a.z, a.w);
            float2 f0 = __bfloat1622float2(h0);
            float2 f1 = __bfloat1622float2(h1);
            __nv_bfloat162 l0 = __floats2bfloat162_rn(a.x - f0.x, a.y - f0.y);
            __nv_bfloat162 l1 = __floats2bfloat162_rn(a.z - f1.x, a.w - f1.y);
            union { __nv_bfloat162 v[2]; uint2 u; } uh, ul;
            uh.v[0] = h0; uh.v[1] = h1;
            ul.v[0] = l0; ul.v[1] = l1;
            *(uint2*)(hi + r * LDK + k) = uh.u;
            *(uint2*)(lo + r * LDK + k) = ul.u;
        }
    }
}

// Transposing: src is [K, N] row-major (ld = N), src points at [k0][n0].
// smem rows are n, cols are k.
__device__ __forceinline__ void load_trans(
    const float* __restrict__ src, int ld,
    __nv_bfloat16* __restrict__ hi, __nv_bfloat16* __restrict__ lo, int t)
{
    const int lane = t & 31, w = t >> 5;
    #pragma unroll
    for (int kk = 0; kk < 2; kk++) {
        const int kp = w * 2 + kk;                 // k-pair 0..15
        const float* r0 = src + (long)(2 * kp) * ld;
        const float* r1 = r0 + ld;
        #pragma unroll
        for (int j = 0; j < 4; j++) {
            const int n = lane + 32 * j;
            float b0 = r0[n], b1 = r1[n];
            __nv_bfloat162 h = __floats2bfloat162_rn(b0, b1);
            float2 hf = __bfloat1622float2(h);
            __nv_bfloat162 l = __floats2bfloat162_rn(b0 - hf.x, b1 - hf.y);
            *(__nv_bfloat162*)(hi + n * LDK + 2 * kp) = h;
            *(__nv_bfloat162*)(lo + n * LDK + 2 * kp) = l;
        }
    }
}

// ===========================================================================
// Tensor-core GEMM via mma.sync: C[M,N] = alpha * A @ op(B) + bias
// TRANSB=true : B is [N,K] row-major -> C = A @ B^T (direct loader)
// TRANSB=false: B is [K,N] row-major -> C = A @ B   (transposing loader)
// ===========================================================================
template<bool TRANSB>
__global__ __launch_bounds__(256, 2)
void gemm_mma(const float* __restrict__ A, const float* __restrict__ B,
              const float* __restrict__ bias, float* __restrict__ C,
              int M, int N, int K, float alpha,
              long sA, long sB, long sC)
{
    A += blockIdx.z * sA;
    B += blockIdx.z * sB;
    C += blockIdx.z * sC;
    const int bm = blockIdx.y * BM;
    const int bn = blockIdx.x * BN;
    const int tid = threadIdx.x;
    const int wid = tid >> 5, lane = tid & 31;
    const int warp_m = wid & 1;   // 2 warps over M (64 rows each)
    const int warp_n = wid >> 1;  // 4 warps over N (32 cols each)

    __shared__ __align__(16) __nv_bfloat16 sAhi[BM * LDK];
    __shared__ __align__(16) __nv_bfloat16 sAlo[BM * LDK];
    __shared__ __align__(16) __nv_bfloat16 sBhi[BN * LDK];
    __shared__ __align__(16) __nv_bfloat16 sBlo[BN * LDK];

    const uint32_t uAhi = smem_u32(sAhi);
    const uint32_t uAlo = smem_u32(sAlo);
    const uint32_t uBhi = smem_u32(sBhi);
    const uint32_t uBlo = smem_u32(sBlo);

    float acc[4][4][4] = {};  // [mi][ni][frag]

    // per-lane ldmatrix address components (element offsets, x2 for bytes)
    const int a_row = warp_m * 64 + (lane & 15);   // + mi*16
    const int a_kb  = (lane >> 4) * 8;             // + ks*16
    const int b_row = warp_n * 32 + (lane & 7);    // + ni*8
    const int b_kb  = ((lane >> 3) & 1) * 8;       // + ks*16

    const int nch = K / BKF;
    for (int c = 0; c < nch; c++) {
        if (c) __syncthreads();

        load_direct(A + (long)bm * K + c * BKF, K, sAhi, sAlo, tid);
        if (TRANSB)
            load_direct(B + (long)bn * K + c * BKF, K, sBhi, sBlo, tid);
        else
            load_trans(B + (long)(c * BKF) * N + bn, N, sBhi, sBlo, tid);

        __syncthreads();

        // 3 split terms: Ahi*Bhi, Ahi*Blo, Alo*Bhi
        #pragma unroll
        for (int term = 0; term < 3; term++) {
            const uint32_t uA = (term == 2) ? uAlo : uAhi;
            const uint32_t uB = (term == 1) ? uBlo : uBhi;
            #pragma unroll
            for (int ks = 0; ks < 2; ks++) {
                uint32_t af[4][4], bf[4][2];
                #pragma unroll
                for (int mi = 0; mi < 4; mi++)
                    ldm_x4(af[mi],
                        uA + (uint32_t)(((a_row + mi * 16) * LDK + a_kb + ks * 16) * 2));
                #pragma unroll
                for (int ni = 0; ni < 4; ni++)
                    ldm_x2(bf[ni],
                        uB + (uint32_t)(((b_row + ni * 8) * LDK + b_kb + ks * 16) * 2));
                #pragma unroll
                for (int mi = 0; mi < 4; mi++)
                    #pragma unroll
                    for (int ni = 0; ni < 4; ni++)
                        mma16816(acc[mi][ni], af[mi], bf[ni]);
            }
        }
    }

    // Epilogue: c-frag -> gmem. frag f: rows (lane>>2) (+8 for f>=2),
    // cols 2*(lane&3) + (f&1).
    const int erow = lane >> 2;
    const int ecol = 2 * (lane & 3);
    #pragma unroll
    for (int mi = 0; mi < 4; mi++) {
        #pragma unroll
        for (int ni = 0; ni < 4; ni++) {
            const int col = bn + warp_n * 32 + ni * 8 + ecol;
            float bx = 0.f, by = 0.f;
            if (bias) { bx = bias[col]; by = bias[col + 1]; }
            {
                const int row = bm + warp_m * 64 + mi * 16 + erow;
                float2 v;
                v.x = acc[mi][ni][0] * alpha + bx;
                v.y = acc[mi][ni][1] * alpha + by;
                *(float2*)(C + (long)row * N + col) = v;
            }
            {
                const int row = bm + warp_m * 64 + mi * 16 + erow + 8;
                float2 v;
                v.x = acc[mi][ni][2] * alpha + bx;
                v.y = acc[mi][ni][3] * alpha + by;
                *(float2*)(C + (long)row * N + col) = v;
            }
        }
    }
}

// ---------------------------------------------------------------------------
// In-place softmax over axis 1 (queries i) of S[b, i, j]; coalesced over j.
// ---------------------------------------------------------------------------
__global__ void softmax_axis1(float* __restrict__ S)
{
    const int j = blockIdx.x * blockDim.x + threadIdx.x;
    const long b = blockIdx.y;
    float* base = S + b * (long)SEQ * SEQ + j;

    float m = -INFINITY, s = 0.0f;
    for (int i = 0; i < SEQ; i++) {
        float x = base[(long)i * SEQ];
        float nm = fmaxf(m, x);
        s = s * __expf(m - nm) + __expf(x - nm);
        m = nm;
    }
    const float inv = 1.0f / s;
    for (int i = 0; i < SEQ; i++) {
        float x = base[(long)i * SEQ];
        base[(long)i * SEQ] = __expf(x - m) * inv;
    }
}

// ---------------------------------------------------------------------------
// kernel_launch
// ---------------------------------------------------------------------------
extern "C" void kernel_launch(void* const* d_in, const int* in_sizes, int n_in,
                              void* d_out, int out_size)
{
    const float* x  = (const float*)d_in[0];
    const float* Wq = (const float*)d_in[1];
    const float* bq = (const float*)d_in[2];
    const float* Wk = (const float*)d_in[3];
    const float* bk = (const float*)d_in[4];
    const float* Wv = (const float*)d_in[5];
    const float* bv = (const float*)d_in[6];

    float* out     = (float*)d_out;
    float* weights = out + (long)BATCH * SEQ * DMODEL;

    float* Q; cudaGetSymbolAddress((void**)&Q, g_Q);
    float* K; cudaGetSymbolAddress((void**)&K, g_K);
    float* V; cudaGetSymbolAddress((void**)&V, g_V);

    const dim3 blk(256);

    // 1) QKV projections: [16384,512] = [16384,512] @ [512,512] + bias (nn)
    {
        dim3 grid(DMODEL / BN, (BATCH * SEQ) / BM, 1);
        gemm_mma<false><<<grid, blk>>>(x, Wq, bq, Q,
            BATCH * SEQ, DMODEL, DMODEL, 1.0f, 0, 0, 0);
        gemm_mma<false><<<grid, blk>>>(x, Wk, bk, K,
            BATCH * SEQ, DMODEL, DMODEL, 1.0f, 0, 0, 0);
        gemm_mma<false><<<grid, blk>>>(x, Wv, bv, V,
            BATCH * SEQ, DMODEL, DMODEL, 1.0f, 0, 0, 0);
    }

    // 2) scores = scale * Q @ K^T per batch (nt), into weights region
    {
        const float scale = 1.0f / sqrtf((float)DMODEL);
        dim3 grid(SEQ / BN, SEQ / BM, BATCH);
        gemm_mma<true><<<grid, blk>>>(Q, K, nullptr, weights,
            SEQ, SEQ, DMODEL, scale,
            (long)SEQ * DMODEL, (long)SEQ * DMODEL, (long)SEQ * SEQ);
    }

    // 3) softmax over axis 1, in place
    {
        dim3 grid(SEQ / 256, BATCH);
        softmax_axis1<<<grid, dim3(256)>>>(weights);
    }

    // 4) out = weights @ V per batch (nn)
    {
        dim3 grid(DMODEL / BN, SEQ / BM, BATCH);
        gemm_mma<false><<<grid, blk>>>(weights, V, nullptr, out,
            SEQ, DMODEL, SEQ, 1.0f,
            (long)SEQ * SEQ, (long)SEQ * DMODEL, (long)SEQ * DMODEL);
    }
}

// round 6
// speedup vs baseline: 2.3429x; 1.0791x over previous
#include <cuda_runtime.h>
#include <cuda_bf16.h>
#include <math.h>
#include <stdint.h>

// Problem constants
#define BATCH 8
#define SEQ   2048
#define DMODEL 512

#define BM 128
#define BN 128
#define BKF 32          // fp32 k per chunk
#define LDK 40          // padded bf16 row stride (32 + 8)

// Per-buffer smem: 4 arrays of 128*40 bf16 = 10240 B each
#define ARR_B   (BM * LDK * 2)
#define BUF_B   (4 * ARR_B)
#define DYN_SMEM (2 * BUF_B)

// Scratch for Q, K, V projections: [B*N, D] each (32 MB each)
__device__ float g_Q[BATCH * SEQ * DMODEL];
__device__ float g_K[BATCH * SEQ * DMODEL];
__device__ float g_V[BATCH * SEQ * DMODEL];

// ===========================================================================
// PTX helpers
// ===========================================================================
__device__ __forceinline__ uint32_t smem_u32(const void* p) {
    uint32_t a;
    asm("{ .reg .u64 t; cvta.to.shared.u64 t, %1; cvt.u32.u64 %0, t; }"
        : "=r"(a) : "l"(p));
    return a;
}

__device__ __forceinline__ void ldm_x4(uint32_t* r, uint32_t addr) {
    asm volatile("ldmatrix.sync.aligned.m8n8.x4.shared.b16 {%0,%1,%2,%3}, [%4];"
        : "=r"(r[0]), "=r"(r[1]), "=r"(r[2]), "=r"(r[3]) : "r"(addr));
}
__device__ __forceinline__ void ldm_x2(uint32_t* r, uint32_t addr) {
    asm volatile("ldmatrix.sync.aligned.m8n8.x2.shared.b16 {%0,%1}, [%2];"
        : "=r"(r[0]), "=r"(r[1]) : "r"(addr));
}

__device__ __forceinline__ void mma16816(float* c, const uint32_t* a, const uint32_t* b) {
    asm volatile(
        "mma.sync.aligned.m16n8k16.row.col.f32.bf16.bf16.f32 "
        "{%0,%1,%2,%3}, {%4,%5,%6,%7}, {%8,%9}, {%0,%1,%2,%3};"
        : "+f"(c[0]), "+f"(c[1]), "+f"(c[2]), "+f"(c[3])
        : "r"(a[0]), "r"(a[1]), "r"(a[2]), "r"(a[3]), "r"(b[0]), "r"(b[1]));
}

// ===========================================================================
// Tile loaders: fp32 gmem -> split bf16 (hi/lo) in padded [row][k] smem.
// Tile = 128 rows x 32 k.
// ===========================================================================
__device__ __forceinline__ void load_direct(
    const float* __restrict__ src, int ld,
    __nv_bfloat16* __restrict__ hi, __nv_bfloat16* __restrict__ lo, int t)
{
    const int kq = (t & 3) * 4;     // 0,4,8,12
    const int r0 = t >> 2;          // 0..63
    #pragma unroll
    for (int rb = 0; rb < 2; rb++) {
        const int r = r0 + rb * 64;
        #pragma unroll
        for (int i = 0; i < 2; i++) {
            const int k = kq + i * 16;
            float4 a = *(const float4*)(src + (long)r * ld + k);
            __nv_bfloat162 h0 = __floats2bfloat162_rn(a.x, a.y);
            __nv_bfloat162 h1 = __floats2bfloat162_rn(a.z, a.w);
            float2 f0 = __bfloat1622float2(h0);
            float2 f1 = __bfloat1622float2(h1);
            __nv_bfloat162 l0 = __floats2bfloat162_rn(a.x - f0.x, a.y - f0.y);
            __nv_bfloat162 l1 = __floats2bfloat162_rn(a.z - f1.x, a.w - f1.y);
            union { __nv_bfloat162 v[2]; uint2 u; } uh, ul;
            uh.v[0] = h0; uh.v[1] = h1;
            ul.v[0] = l0; ul.v[1] = l1;
            *(uint2*)(hi + r * LDK + k) = uh.u;
            *(uint2*)(lo + r * LDK + k) = ul.u;
        }
    }
}

__device__ __forceinline__ void load_trans(
    const float* __restrict__ src, int ld,
    __nv_bfloat16* __restrict__ hi, __nv_bfloat16* __restrict__ lo, int t)
{
    const int lane = t & 31, w = t >> 5;
    #pragma unroll
    for (int kk = 0; kk < 2; kk++) {
        const int kp = w * 2 + kk;                 // k-pair 0..15
        const float* r0 = src + (long)(2 * kp) * ld;
        const float* r1 = r0 + ld;
        #pragma unroll
        for (int j = 0; j < 4; j++) {
            const int n = lane + 32 * j;
            float b0 = r0[n], b1 = r1[n];
            __nv_bfloat162 h = __floats2bfloat162_rn(b0, b1);
            float2 hf = __bfloat1622float2(h);
            __nv_bfloat162 l = __floats2bfloat162_rn(b0 - hf.x, b1 - hf.y);
            *(__nv_bfloat162*)(hi + n * LDK + 2 * kp) = h;
            *(__nv_bfloat162*)(lo + n * LDK + 2 * kp) = l;
        }
    }
}

// ===========================================================================
// Tensor-core GEMM via mma.sync: C[M,N] = alpha * A @ op(B) + bias
// Double-buffered smem; 3-term bf16 split with fragment reuse.
// ===========================================================================
template<bool TRANSB>
__global__ __launch_bounds__(256, 2)
void gemm_mma(const float* __restrict__ A, const float* __restrict__ B,
              const float* __restrict__ bias, float* __restrict__ C,
              int M, int N, int K, float alpha,
              long sA, long sB, long sC)
{
    A += blockIdx.z * sA;
    B += blockIdx.z * sB;
    C += blockIdx.z * sC;
    const int bm = blockIdx.y * BM;
    const int bn = blockIdx.x * BN;
    const int tid = threadIdx.x;
    const int wid = tid >> 5, lane = tid & 31;
    const int warp_m = wid & 1;   // 2 warps over M (64 rows each)
    const int warp_n = wid >> 1;  // 4 warps over N (32 cols each)

    extern __shared__ __align__(16) char dynsmem[];

    float acc[4][4][4] = {};  // [mi][ni][frag]

    // per-lane ldmatrix address components (element offsets)
    const int a_row = warp_m * 64 + (lane & 15);
    const int a_kb  = (lane >> 4) * 8;
    const int b_row = warp_n * 32 + (lane & 7);
    const int b_kb  = ((lane >> 3) & 1) * 8;

    const int nch = K / BKF;

    // Prologue: fill buffer 0 with chunk 0
    {
        __nv_bfloat16* Ahi = (__nv_bfloat16*)(dynsmem);
        __nv_bfloat16* Alo = (__nv_bfloat16*)(dynsmem + ARR_B);
        __nv_bfloat16* Bhi = (__nv_bfloat16*)(dynsmem + 2 * ARR_B);
        __nv_bfloat16* Blo = (__nv_bfloat16*)(dynsmem + 3 * ARR_B);
        load_direct(A + (long)bm * K, K, Ahi, Alo, tid);
        if (TRANSB) load_direct(B + (long)bn * K, K, Bhi, Blo, tid);
        else        load_trans(B + bn, N, Bhi, Blo, tid);
    }
    __syncthreads();

    for (int c = 0; c < nch; c++) {
        char* buf = dynsmem + (c & 1) * BUF_B;
        const uint32_t uAhi = smem_u32(buf);
        const uint32_t uAlo = uAhi + ARR_B;
        const uint32_t uBhi = uAhi + 2 * ARR_B;
        const uint32_t uBlo = uAhi + 3 * ARR_B;

        // ---- MMA on current buffer (fragments loaded once per ks) ----
        #pragma unroll
        for (int ks = 0; ks < 2; ks++) {
            const uint32_t aoff = (uint32_t)((a_kb + ks * 16) * 2);
            const uint32_t boff = (uint32_t)((b_kb + ks * 16) * 2);
            uint32_t afh[4][4], afl[4][4], bfh[4][2], bfl[4][2];
            #pragma unroll
            for (int mi = 0; mi < 4; mi++)
                ldm_x4(afh[mi], uAhi + (uint32_t)((a_row + mi * 16) * LDK * 2) + aoff);
            #pragma unroll
            for (int ni = 0; ni < 4; ni++)
                ldm_x2(bfh[ni], uBhi + (uint32_t)((b_row + ni * 8) * LDK * 2) + boff);
            #pragma unroll
            for (int mi = 0; mi < 4; mi++)
                #pragma unroll
                for (int ni = 0; ni < 4; ni++)
                    mma16816(acc[mi][ni], afh[mi], bfh[ni]);
            #pragma unroll
            for (int ni = 0; ni < 4; ni++)
                ldm_x2(bfl[ni], uBlo + (uint32_t)((b_row + ni * 8) * LDK * 2) + boff);
            #pragma unroll
            for (int mi = 0; mi < 4; mi++)
                #pragma unroll
                for (int ni = 0; ni < 4; ni++)
                    mma16816(acc[mi][ni], afh[mi], bfl[ni]);
            #pragma unroll
            for (int mi = 0; mi < 4; mi++)
                ldm_x4(afl[mi], uAlo + (uint32_t)((a_row + mi * 16) * LDK * 2) + aoff);
            #pragma unroll
            for (int mi = 0; mi < 4; mi++)
                #pragma unroll
                for (int ni = 0; ni < 4; ni++)
                    mma16816(acc[mi][ni], afl[mi], bfh[ni]);
        }

        // ---- Prefetch next chunk into the other buffer ----
        if (c + 1 < nch) {
            char* nb = dynsmem + ((c + 1) & 1) * BUF_B;
            __nv_bfloat16* Ahi = (__nv_bfloat16*)(nb);
            __nv_bfloat16* Alo = (__nv_bfloat16*)(nb + ARR_B);
            __nv_bfloat16* Bhi = (__nv_bfloat16*)(nb + 2 * ARR_B);
            __nv_bfloat16* Blo = (__nv_bfloat16*)(nb + 3 * ARR_B);
            const int k0 = (c + 1) * BKF;
            load_direct(A + (long)bm * K + k0, K, Ahi, Alo, tid);
            if (TRANSB) load_direct(B + (long)bn * K + k0, K, Bhi, Blo, tid);
            else        load_trans(B + (long)k0 * N + bn, N, Bhi, Blo, tid);
        }
        __syncthreads();
    }

    // Epilogue
    const int erow = lane >> 2;
    const int ecol = 2 * (lane & 3);
    #pragma unroll
    for (int mi = 0; mi < 4; mi++) {
        #pragma unroll
        for (int ni = 0; ni < 4; ni++) {
            const int col = bn + warp_n * 32 + ni * 8 + ecol;
            float bx = 0.f, by = 0.f;
            if (bias) { bx = bias[col]; by = bias[col + 1]; }
            {
                const int row = bm + warp_m * 64 + mi * 16 + erow;
                float2 v;
                v.x = acc[mi][ni][0] * alpha + bx;
                v.y = acc[mi][ni][1] * alpha + by;
                *(float2*)(C + (long)row * N + col) = v;
            }
            {
                const int row = bm + warp_m * 64 + mi * 16 + erow + 8;
                float2 v;
                v.x = acc[mi][ni][2] * alpha + bx;
                v.y = acc[mi][ni][3] * alpha + by;
                *(float2*)(C + (long)row * N + col) = v;
            }
        }
    }
}

// ---------------------------------------------------------------------------
// In-place softmax over axis 1 (queries i) of S[b, i, j]; coalesced over j.
// ---------------------------------------------------------------------------
__global__ void softmax_axis1(float* __restrict__ S)
{
    const int j = blockIdx.x * blockDim.x + threadIdx.x;
    const long b = blockIdx.y;
    float* base = S + b * (long)SEQ * SEQ + j;

    float m = -INFINITY, s = 0.0f;
    for (int i = 0; i < SEQ; i++) {
        float x = base[(long)i * SEQ];
        float nm = fmaxf(m, x);
        s = s * __expf(m - nm) + __expf(x - nm);
        m = nm;
    }
    const float inv = 1.0f / s;
    for (int i = 0; i < SEQ; i++) {
        float x = base[(long)i * SEQ];
        base[(long)i * SEQ] = __expf(x - m) * inv;
    }
}

// ---------------------------------------------------------------------------
// kernel_launch
// ---------------------------------------------------------------------------
extern "C" void kernel_launch(void* const* d_in, const int* in_sizes, int n_in,
                              void* d_out, int out_size)
{
    const float* x  = (const float*)d_in[0];
    const float* Wq = (const float*)d_in[1];
    const float* bq = (const float*)d_in[2];
    const float* Wk = (const float*)d_in[3];
    const float* bk = (const float*)d_in[4];
    const float* Wv = (const float*)d_in[5];
    const float* bv = (const float*)d_in[6];

    float* out     = (float*)d_out;
    float* weights = out + (long)BATCH * SEQ * DMODEL;

    float* Q; cudaGetSymbolAddress((void**)&Q, g_Q);
    float* K; cudaGetSymbolAddress((void**)&K, g_K);
    float* V; cudaGetSymbolAddress((void**)&V, g_V);

    static bool attr_set = false;
    if (!attr_set) {
        cudaFuncSetAttribute(gemm_mma<false>,
                             cudaFuncAttributeMaxDynamicSharedMemorySize, DYN_SMEM);
        cudaFuncSetAttribute(gemm_mma<true>,
                             cudaFuncAttributeMaxDynamicSharedMemorySize, DYN_SMEM);
        attr_set = true;
    }

    const dim3 blk(256);

    // 1) QKV projections (nn)
    {
        dim3 grid(DMODEL / BN, (BATCH * SEQ) / BM, 1);
        gemm_mma<false><<<grid, blk, DYN_SMEM>>>(x, Wq, bq, Q,
            BATCH * SEQ, DMODEL, DMODEL, 1.0f, 0, 0, 0);
        gemm_mma<false><<<grid, blk, DYN_SMEM>>>(x, Wk, bk, K,
            BATCH * SEQ, DMODEL, DMODEL, 1.0f, 0, 0, 0);
        gemm_mma<false><<<grid, blk, DYN_SMEM>>>(x, Wv, bv, V,
            BATCH * SEQ, DMODEL, DMODEL, 1.0f, 0, 0, 0);
    }

    // 2) scores = scale * Q @ K^T per batch (nt)
    {
        const float scale = 1.0f / sqrtf((float)DMODEL);
        dim3 grid(SEQ / BN, SEQ / BM, BATCH);
        gemm_mma<true><<<grid, blk, DYN_SMEM>>>(Q, K, nullptr, weights,
            SEQ, SEQ, DMODEL, scale,
            (long)SEQ * DMODEL, (long)SEQ * DMODEL, (long)SEQ * SEQ);
    }

    // 3) softmax over axis 1, in place
    {
        dim3 grid(SEQ / 256, BATCH);
        softmax_axis1<<<grid, dim3(256)>>>(weights);
    }

    // 4) out = weights @ V per batch (nn)
    {
        dim3 grid(DMODEL / BN, SEQ / BM, BATCH);
        gemm_mma<false><<<grid, blk, DYN_SMEM>>>(weights, V, nullptr, out,
            SEQ, DMODEL, SEQ, 1.0f,
            (long)SEQ * SEQ, (long)SEQ * DMODEL, (long)SEQ * DMODEL);
    }
}

// round 7
// speedup vs baseline: 2.7676x; 1.1812x over previous
#include <cuda_runtime.h>
#include <cuda_bf16.h>
#include <math.h>
#include <stdint.h>

// Problem constants
#define BATCH 8
#define SEQ   2048
#define DMODEL 512

#define BM 128
#define BN 128
#define BKE 32          // bf16 k elements per chunk (two k16 steps)
#define LDK 40          // padded bf16 row stride (32 data + 8 pad) = 80 B

#define ARR_B   (BM * LDK * 2)      // 10240 B per array
#define BUF_B   (4 * ARR_B)         // Ahi,Alo,Bhi,Blo
#define DYN_SMEM (2 * BUF_B)        // double buffered (80 KB)

#define ICH 16                      // softmax i-chunks
#define RPI (SEQ / ICH)             // 128 rows per chunk

typedef __nv_bfloat16 bf16;
typedef __nv_bfloat162 bf162;

// ---------------------------------------------------------------------------
// Device scratch (allocation-guard-safe)
// ---------------------------------------------------------------------------
__device__ bf16 g_xhi[BATCH * SEQ * DMODEL], g_xlo[BATCH * SEQ * DMODEL];
__device__ bf16 g_Wthi[3 * DMODEL * DMODEL], g_Wtlo[3 * DMODEL * DMODEL];
__device__ bf16 g_Qhi[BATCH * SEQ * DMODEL], g_Qlo[BATCH * SEQ * DMODEL];
__device__ bf16 g_Khi[BATCH * SEQ * DMODEL], g_Klo[BATCH * SEQ * DMODEL];
__device__ bf16 g_Vhi[BATCH * SEQ * DMODEL], g_Vlo[BATCH * SEQ * DMODEL];
__device__ bf16 g_Vthi[BATCH * DMODEL * SEQ], g_Vtlo[BATCH * DMODEL * SEQ];
__device__ bf16 g_Whi[(long)BATCH * SEQ * SEQ], g_Wlo[(long)BATCH * SEQ * SEQ];
__device__ float g_pm[BATCH * ICH * SEQ], g_ps[BATCH * ICH * SEQ];
__device__ float g_gm[BATCH * SEQ], g_gi[BATCH * SEQ];

// ---------------------------------------------------------------------------
// PTX helpers
// ---------------------------------------------------------------------------
__device__ __forceinline__ uint32_t smem_u32(const void* p) {
    uint32_t a;
    asm("{ .reg .u64 t; cvta.to.shared.u64 t, %1; cvt.u32.u64 %0, t; }"
        : "=r"(a) : "l"(p));
    return a;
}
__device__ __forceinline__ void ldm_x4(uint32_t* r, uint32_t addr) {
    asm volatile("ldmatrix.sync.aligned.m8n8.x4.shared.b16 {%0,%1,%2,%3}, [%4];"
        : "=r"(r[0]), "=r"(r[1]), "=r"(r[2]), "=r"(r[3]) : "r"(addr));
}
__device__ __forceinline__ void mma16816(float* c, const uint32_t* a, const uint32_t* b) {
    asm volatile(
        "mma.sync.aligned.m16n8k16.row.col.f32.bf16.bf16.f32 "
        "{%0,%1,%2,%3}, {%4,%5,%6,%7}, {%8,%9}, {%0,%1,%2,%3};"
        : "+f"(c[0]), "+f"(c[1]), "+f"(c[2]), "+f"(c[3])
        : "r"(a[0]), "r"(a[1]), "r"(a[2]), "r"(a[3]), "r"(b[0]), "r"(b[1]));
}
__device__ __forceinline__ void cp16(uint32_t dst, const void* src) {
    asm volatile("cp.async.cg.shared.global [%0], [%1], 16;"
        :: "r"(dst), "l"(src) : "memory");
}
#define CP_COMMIT() asm volatile("cp.async.commit_group;" ::: "memory")
#define CP_WAIT0()  asm volatile("cp.async.wait_group 0;" ::: "memory")
#define CP_WAIT1()  asm volatile("cp.async.wait_group 1;" ::: "memory")

__device__ __forceinline__ void split1(float a, bf16& h, bf16& l) {
    h = __float2bfloat16_rn(a);
    l = __float2bfloat16_rn(a - __bfloat162float(h));
}

// ---------------------------------------------------------------------------
// cp.async tile load: 128 rows x 32 bf16 (64 B data / row) from K-major gmem.
// src points at [row0][k0]; ld in elements. 512 16B chunks, 2 per thread.
// ---------------------------------------------------------------------------
__device__ __forceinline__ void cpa_tile(const bf16* __restrict__ src, int ld,
                                         uint32_t arr, int t)
{
    #pragma unroll
    for (int i = 0; i < 2; i++) {
        const int c = t + i * 256;
        const int r = c >> 2;
        const int kb = (c & 3) * 16;
        cp16(arr + r * (LDK * 2) + kb, (const char*)(src + (long)r * ld) + kb);
    }
}

// ===========================================================================
// GEMM on pre-split bf16: C[M,N] = alpha*(Ahi+Alo)@(Bhi+Blo)^T + bias
// A: [M,K] K-major. B: [N,K] K-major. 3-term split (hh + hl + lh).
// Outputs: optional fp32 C, optional split bf16 (Chi, Clo).
// ===========================================================================
__global__ __launch_bounds__(256, 2)
void gemm_ps(const bf16* __restrict__ Ahi, const bf16* __restrict__ Alo,
             const bf16* __restrict__ Bhi, const bf16* __restrict__ Blo,
             const float* __restrict__ bias, float alpha,
             int M, int N, int K, long sA, long sB, long sC,
             float* __restrict__ Cf, bf16* __restrict__ Chi, bf16* __restrict__ Clo)
{
    const long za = (long)blockIdx.z * sA;
    const long zb = (long)blockIdx.z * sB;
    const long zc = (long)blockIdx.z * sC;
    const int bm = blockIdx.y * BM;
    const int bn = blockIdx.x * BN;
    const int tid = threadIdx.x;
    const int wid = tid >> 5, lane = tid & 31;
    const int warp_m = wid & 1;
    const int warp_n = wid >> 1;

    extern __shared__ __align__(16) char dynsmem[];
    const uint32_t sbase = smem_u32(dynsmem);

    float acc[4][4][4] = {};

    // ldmatrix lane-address components
    const int a_row = warp_m * 64 + (lane & 15);
    const int a_kb  = (lane >> 4) * 8;
    // B x4: matrices (ni, k0),(ni, k8),(ni+1, k0),(ni+1, k8)
    const int b_row = warp_n * 32 + (lane & 7) + ((lane >> 4) * 8);
    const int b_kb  = ((lane >> 3) & 1) * 8;

    const int nch = K / BKE;

    // Prologue: chunk 0 -> buf 0
    {
        const uint32_t b0 = sbase;
        cpa_tile(Ahi + za + (long)bm * K, K, b0 + 0 * ARR_B, tid);
        cpa_tile(Alo + za + (long)bm * K, K, b0 + 1 * ARR_B, tid);
        cpa_tile(Bhi + zb + (long)bn * K, K, b0 + 2 * ARR_B, tid);
        cpa_tile(Blo + zb + (long)bn * K, K, b0 + 3 * ARR_B, tid);
        CP_COMMIT();
    }

    for (int c = 0; c < nch; c++) {
        if (c + 1 < nch) {
            const uint32_t nb = sbase + ((c + 1) & 1) * BUF_B;
            const int k0 = (c + 1) * BKE;
            cpa_tile(Ahi + za + (long)bm * K + k0, K, nb + 0 * ARR_B, tid);
            cpa_tile(Alo + za + (long)bm * K + k0, K, nb + 1 * ARR_B, tid);
            cpa_tile(Bhi + zb + (long)bn * K + k0, K, nb + 2 * ARR_B, tid);
            cpa_tile(Blo + zb + (long)bn * K + k0, K, nb + 3 * ARR_B, tid);
            CP_COMMIT();
            CP_WAIT1();
        } else {
            CP_WAIT0();
        }
        __syncthreads();

        const uint32_t buf = sbase + (c & 1) * BUF_B;
        const uint32_t uAhi = buf, uAlo = buf + ARR_B;
        const uint32_t uBhi = buf + 2 * ARR_B, uBlo = buf + 3 * ARR_B;

        #pragma unroll
        for (int ks = 0; ks < 2; ks++) {
            const uint32_t aoff = (uint32_t)((a_kb + ks * 16) * 2);
            const uint32_t boff = (uint32_t)((b_kb + ks * 16) * 2);
            uint32_t afh[4][4], afl[4][4], bfh[2][4], bfl[2][4];
            #pragma unroll
            for (int mi = 0; mi < 4; mi++)
                ldm_x4(afh[mi], uAhi + (uint32_t)((a_row + mi * 16) * LDK * 2) + aoff);
            #pragma unroll
            for (int nb = 0; nb < 2; nb++)
                ldm_x4(bfh[nb], uBhi + (uint32_t)((b_row + nb * 16) * LDK * 2) + boff);
            #pragma unroll
            for (int mi = 0; mi < 4; mi++)
                #pragma unroll
                for (int ni = 0; ni < 4; ni++)
                    mma16816(acc[mi][ni], afh[mi], &bfh[ni >> 1][(ni & 1) * 2]);
            #pragma unroll
            for (int nb = 0; nb < 2; nb++)
                ldm_x4(bfl[nb], uBlo + (uint32_t)((b_row + nb * 16) * LDK * 2) + boff);
            #pragma unroll
            for (int mi = 0; mi < 4; mi++)
                #pragma unroll
                for (int ni = 0; ni < 4; ni++)
                    mma16816(acc[mi][ni], afh[mi], &bfl[ni >> 1][(ni & 1) * 2]);
            #pragma unroll
            for (int mi = 0; mi < 4; mi++)
                ldm_x4(afl[mi], uAlo + (uint32_t)((a_row + mi * 16) * LDK * 2) + aoff);
            #pragma unroll
            for (int mi = 0; mi < 4; mi++)
                #pragma unroll
                for (int ni = 0; ni < 4; ni++)
                    mma16816(acc[mi][ni], afl[mi], &bfh[ni >> 1][(ni & 1) * 2]);
        }
        __syncthreads();
    }

    // Epilogue
    const int erow = lane >> 2;
    const int ecol = 2 * (lane & 3);
    #pragma unroll
    for (int mi = 0; mi < 4; mi++) {
        #pragma unroll
        for (int ni = 0; ni < 4; ni++) {
            const int col = bn + warp_n * 32 + ni * 8 + ecol;
            float bx = 0.f, by = 0.f;
            if (bias) { bx = bias[col]; by = bias[col + 1]; }
            #pragma unroll
            for (int h = 0; h < 2; h++) {
                const int row = bm + warp_m * 64 + mi * 16 + erow + h * 8;
                float vx = acc[mi][ni][2 * h + 0] * alpha + bx;
                float vy = acc[mi][ni][2 * h + 1] * alpha + by;
                const long off = zc + (long)row * N + col;
                if (Cf) *(float2*)(Cf + off) = make_float2(vx, vy);
                if (Chi) {
                    bf162 hh = __floats2bfloat162_rn(vx, vy);
                    float2 hf = __bfloat1622float2(hh);
                    bf162 ll = __floats2bfloat162_rn(vx - hf.x, vy - hf.y);
                    *(bf162*)(Chi + off) = hh;
                    *(bf162*)(Clo + off) = ll;
                }
            }
        }
    }
}

// ---------------------------------------------------------------------------
// split_x: fp32 -> hi/lo bf16 elementwise (vectorized by 4)
// ---------------------------------------------------------------------------
__global__ void split_fp32(const float* __restrict__ src,
                           bf16* __restrict__ hi, bf16* __restrict__ lo, long n4)
{
    const long i = (long)blockIdx.x * blockDim.x + threadIdx.x;
    if (i >= n4) return;
    float4 a = ((const float4*)src)[i];
    bf162 h0 = __floats2bfloat162_rn(a.x, a.y);
    bf162 h1 = __floats2bfloat162_rn(a.z, a.w);
    float2 f0 = __bfloat1622float2(h0);
    float2 f1 = __bfloat1622float2(h1);
    bf162 l0 = __floats2bfloat162_rn(a.x - f0.x, a.y - f0.y);
    bf162 l1 = __floats2bfloat162_rn(a.z - f1.x, a.w - f1.y);
    ((bf162*)hi)[2 * i] = h0; ((bf162*)hi)[2 * i + 1] = h1;
    ((bf162*)lo)[2 * i] = l0; ((bf162*)lo)[2 * i + 1] = l1;
}

// ---------------------------------------------------------------------------
// Transpose + split: W fp32 [K=512][N=512] -> Wt split bf16 [n][k]
// ---------------------------------------------------------------------------
__global__ void transpose_split_w(const float* __restrict__ W,
                                  bf16* __restrict__ Thi, bf16* __restrict__ Tlo)
{
    __shared__ float tile[32][33];
    const int k0 = blockIdx.y * 32, n0 = blockIdx.x * 32;
    const int tx = threadIdx.x, ty = threadIdx.y;
    #pragma unroll
    for (int yy = 0; yy < 32; yy += 8)
        tile[ty + yy][tx] = W[(long)(k0 + ty + yy) * DMODEL + n0 + tx];
    __syncthreads();
    #pragma unroll
    for (int yy = 0; yy < 32; yy += 8) {
        float v = tile[tx][ty + yy];
        bf16 h, l; split1(v, h, l);
        Thi[(long)(n0 + ty + yy) * DMODEL + k0 + tx] = h;
        Tlo[(long)(n0 + ty + yy) * DMODEL + k0 + tx] = l;
    }
}

// ---------------------------------------------------------------------------
// Transpose split-bf16 V [b*N + n][e] -> Vt [b][e][n]
// ---------------------------------------------------------------------------
__global__ void transpose_v(const bf16* __restrict__ Vhi, const bf16* __restrict__ Vlo,
                            bf16* __restrict__ Thi, bf16* __restrict__ Tlo)
{
    __shared__ bf16 th[32][33], tl[32][33];
    const long b = blockIdx.z;
    const int e0 = blockIdx.x * 32, n0 = blockIdx.y * 32;
    const int tx = threadIdx.x, ty = threadIdx.y;
    #pragma unroll
    for (int yy = 0; yy < 32; yy += 8) {
        const long src = (b * SEQ + n0 + ty + yy) * DMODEL + e0 + tx;
        th[ty + yy][tx] = Vhi[src];
        tl[ty + yy][tx] = Vlo[src];
    }
    __syncthreads();
    #pragma unroll
    for (int yy = 0; yy < 32; yy += 8) {
        const long dst = b * DMODEL * SEQ + (long)(e0 + ty + yy) * SEQ + n0 + tx;
        Thi[dst] = th[tx][ty + yy];
        Tlo[dst] = tl[tx][ty + yy];
    }
}

// ---------------------------------------------------------------------------
// Softmax over axis 1 (queries i), 3 passes
// ---------------------------------------------------------------------------
__global__ void sm_pass1(const float* __restrict__ S,
                         float* __restrict__ pm, float* __restrict__ ps)
{
    const int j = blockIdx.x * blockDim.x + threadIdx.x;
    const int ic = blockIdx.y;
    const long b = blockIdx.z;
    const float* base = S + b * (long)SEQ * SEQ + (long)ic * RPI * SEQ + j;
    float m = -INFINITY, s = 0.0f;
    #pragma unroll 4
    for (int i = 0; i < RPI; i++) {
        float x = base[(long)i * SEQ];
        float nm = fmaxf(m, x);
        s = s * __expf(m - nm) + __expf(x - nm);
        m = nm;
    }
    pm[(b * ICH + ic) * SEQ + j] = m;
    ps[(b * ICH + ic) * SEQ + j] = s;
}

__global__ void sm_pass2(const float* __restrict__ pm, const float* __restrict__ ps,
                         float* __restrict__ gm, float* __restrict__ gi)
{
    const int j = blockIdx.x * blockDim.x + threadIdx.x;
    const long b = blockIdx.y;
    float m = -INFINITY;
    #pragma unroll
    for (int ic = 0; ic < ICH; ic++)
        m = fmaxf(m, pm[(b * ICH + ic) * SEQ + j]);
    float s = 0.0f;
    #pragma unroll
    for (int ic = 0; ic < ICH; ic++)
        s += ps[(b * ICH + ic) * SEQ + j] * __expf(pm[(b * ICH + ic) * SEQ + j] - m);
    gm[b * SEQ + j] = m;
    gi[b * SEQ + j] = 1.0f / s;
}

__global__ void sm_pass3(float* __restrict__ S,
                         const float* __restrict__ gm, const float* __restrict__ gi,
                         bf16* __restrict__ whi, bf16* __restrict__ wlo)
{
    const int j4 = (blockIdx.x * blockDim.x + threadIdx.x) * 4;
    const int i = blockIdx.y;
    const long b = blockIdx.z;
    const long off = b * (long)SEQ * SEQ + (long)i * SEQ + j4;
    float4 x = *(const float4*)(S + off);
    float4 m = *(const float4*)(gm + b * SEQ + j4);
    float4 v = *(const float4*)(gi + b * SEQ + j4);
    float4 w;
    w.x = __expf(x.x - m.x) * v.x;
    w.y = __expf(x.y - m.y) * v.y;
    w.z = __expf(x.z - m.z) * v.z;
    w.w = __expf(x.w - m.w) * v.w;
    *(float4*)(S + off) = w;
    bf162 h0 = __floats2bfloat162_rn(w.x, w.y);
    bf162 h1 = __floats2bfloat162_rn(w.z, w.w);
    float2 f0 = __bfloat1622float2(h0);
    float2 f1 = __bfloat1622float2(h1);
    bf162 l0 = __floats2bfloat162_rn(w.x - f0.x, w.y - f0.y);
    bf162 l1 = __floats2bfloat162_rn(w.z - f1.x, w.w - f1.y);
    *(bf162*)(whi + off) = h0; *(bf162*)(whi + off + 2) = h1;
    *(bf162*)(wlo + off) = l0; *(bf162*)(wlo + off + 2) = l1;
}

// ---------------------------------------------------------------------------
// kernel_launch
// ---------------------------------------------------------------------------
extern "C" void kernel_launch(void* const* d_in, const int* in_sizes, int n_in,
                              void* d_out, int out_size)
{
    const float* x  = (const float*)d_in[0];
    const float* Wq = (const float*)d_in[1];
    const float* bq = (const float*)d_in[2];
    const float* Wk = (const float*)d_in[3];
    const float* bk = (const float*)d_in[4];
    const float* Wv = (const float*)d_in[5];
    const float* bv = (const float*)d_in[6];

    float* out     = (float*)d_out;
    float* weights = out + (long)BATCH * SEQ * DMODEL;

    bf16 *xhi, *xlo, *Wthi, *Wtlo, *Qhi, *Qlo, *Khi, *Klo, *Vhi, *Vlo;
    bf16 *Vthi, *Vtlo, *Whi, *Wlo;
    float *pm, *ps, *gm, *gi;
    cudaGetSymbolAddress((void**)&xhi, g_xhi);   cudaGetSymbolAddress((void**)&xlo, g_xlo);
    cudaGetSymbolAddress((void**)&Wthi, g_Wthi); cudaGetSymbolAddress((void**)&Wtlo, g_Wtlo);
    cudaGetSymbolAddress((void**)&Qhi, g_Qhi);   cudaGetSymbolAddress((void**)&Qlo, g_Qlo);
    cudaGetSymbolAddress((void**)&Khi, g_Khi);   cudaGetSymbolAddress((void**)&Klo, g_Klo);
    cudaGetSymbolAddress((void**)&Vhi, g_Vhi);   cudaGetSymbolAddress((void**)&Vlo, g_Vlo);
    cudaGetSymbolAddress((void**)&Vthi, g_Vthi); cudaGetSymbolAddress((void**)&Vtlo, g_Vtlo);
    cudaGetSymbolAddress((void**)&Whi, g_Whi);   cudaGetSymbolAddress((void**)&Wlo, g_Wlo);
    cudaGetSymbolAddress((void**)&pm, g_pm);     cudaGetSymbolAddress((void**)&ps, g_ps);
    cudaGetSymbolAddress((void**)&gm, g_gm);     cudaGetSymbolAddress((void**)&gi, g_gi);

    static bool attr_set = false;
    if (!attr_set) {
        cudaFuncSetAttribute(gemm_ps,
                             cudaFuncAttributeMaxDynamicSharedMemorySize, DYN_SMEM);
        attr_set = true;
    }

    const dim3 blk(256);
    const long MD = (long)BATCH * SEQ * DMODEL;

    // 0) split inputs
    split_fp32<<<(unsigned)((MD / 4 + 255) / 256), blk>>>(x, xhi, xlo, MD / 4);
    {
        dim3 g(16, 16), b(32, 8);
        transpose_split_w<<<g, b>>>(Wq, Wthi + 0 * DMODEL * DMODEL, Wtlo + 0 * DMODEL * DMODEL);
        transpose_split_w<<<g, b>>>(Wk, Wthi + 1 * DMODEL * DMODEL, Wtlo + 1 * DMODEL * DMODEL);
        transpose_split_w<<<g, b>>>(Wv, Wthi + 2 * DMODEL * DMODEL, Wtlo + 2 * DMODEL * DMODEL);
    }

    // 1) projections -> split bf16 Q, K, V
    {
        dim3 grid(DMODEL / BN, (BATCH * SEQ) / BM, 1);
        gemm_ps<<<grid, blk, DYN_SMEM>>>(xhi, xlo,
            Wthi + 0 * DMODEL * DMODEL, Wtlo + 0 * DMODEL * DMODEL, bq, 1.0f,
            BATCH * SEQ, DMODEL, DMODEL, 0, 0, 0, nullptr, Qhi, Qlo);
        gemm_ps<<<grid, blk, DYN_SMEM>>>(xhi, xlo,
            Wthi + 1 * DMODEL * DMODEL, Wtlo + 1 * DMODEL * DMODEL, bk, 1.0f,
            BATCH * SEQ, DMODEL, DMODEL, 0, 0, 0, nullptr, Khi, Klo);
        gemm_ps<<<grid, blk, DYN_SMEM>>>(xhi, xlo,
            Wthi + 2 * DMODEL * DMODEL, Wtlo + 2 * DMODEL * DMODEL, bv, 1.0f,
            BATCH * SEQ, DMODEL, DMODEL, 0, 0, 0, nullptr, Vhi, Vlo);
    }

    // 1b) V -> Vt (per batch [e][n])
    {
        dim3 g(DMODEL / 32, SEQ / 32, BATCH), b(32, 8);
        transpose_v<<<g, b>>>(Vhi, Vlo, Vthi, Vtlo);
    }

    // 2) scores = scale * Q @ K^T -> weights (fp32)
    {
        const float scale = 1.0f / sqrtf((float)DMODEL);
        dim3 grid(SEQ / BN, SEQ / BM, BATCH);
        gemm_ps<<<grid, blk, DYN_SMEM>>>(Qhi, Qlo, Khi, Klo, nullptr, scale,
            SEQ, SEQ, DMODEL, (long)SEQ * DMODEL, (long)SEQ * DMODEL,
            (long)SEQ * SEQ, weights, nullptr, nullptr);
    }

    // 3) softmax over axis 1 (3 passes); pass3 also emits split bf16 weights
    {
        dim3 g1(SEQ / 256, ICH, BATCH);
        sm_pass1<<<g1, blk>>>(weights, pm, ps);
        dim3 g2(SEQ / 256, BATCH);
        sm_pass2<<<g2, blk>>>(pm, ps, gm, gi);
        dim3 g3(SEQ / (256 * 4), SEQ, BATCH);
        sm_pass3<<<g3, blk>>>(weights, gm, gi, Whi, Wlo);
    }

    // 4) out = weights @ V  (B = Vt [e][j], K-major over j)
    {
        dim3 grid(DMODEL / BN, SEQ / BM, BATCH);
        gemm_ps<<<grid, blk, DYN_SMEM>>>(Whi, Wlo, Vthi, Vtlo, nullptr, 1.0f,
            SEQ, DMODEL, SEQ, (long)SEQ * SEQ, (long)DMODEL * SEQ,
            (long)SEQ * DMODEL, out, nullptr, nullptr);
    }
}

// round 8
// speedup vs baseline: 3.0505x; 1.1022x over previous
#include <cuda_runtime.h>
#include <cuda_bf16.h>
#include <math.h>
#include <stdint.h>

// Problem constants
#define BATCH 8
#define SEQ   2048
#define DMODEL 512

#define BM 128
#define BN 128
#define BKE 32                // bf16 k elements per chunk (two k16 steps)

// SW128-swizzled tile: 128 rows x 128 B (hi bytes [0,64), lo bytes [64,128))
#define TILE_B  16384
#define STAGE_B (2 * TILE_B)  // A tile + B tile
#define NSTAGE  3
#define DYN_SMEM (NSTAGE * STAGE_B)   // 96 KB

#define ICH 16                // softmax i-chunks == SEQ/BM
#define MODE_PROJ   0
#define MODE_SCORES 1
#define MODE_AV     2

typedef __nv_bfloat16 bf16;
typedef __nv_bfloat162 bf162;

// ---------------------------------------------------------------------------
// Device scratch (allocation-guard-safe)
// ---------------------------------------------------------------------------
__device__ bf16 g_xhi[BATCH * SEQ * DMODEL], g_xlo[BATCH * SEQ * DMODEL];
__device__ bf16 g_Wthi[3 * DMODEL * DMODEL], g_Wtlo[3 * DMODEL * DMODEL];
__device__ bf16 g_Qhi[BATCH * SEQ * DMODEL], g_Qlo[BATCH * SEQ * DMODEL];
__device__ bf16 g_Khi[BATCH * SEQ * DMODEL], g_Klo[BATCH * SEQ * DMODEL];
__device__ bf16 g_Vhi[BATCH * SEQ * DMODEL], g_Vlo[BATCH * SEQ * DMODEL];
__device__ bf16 g_Vthi[BATCH * DMODEL * SEQ], g_Vtlo[BATCH * DMODEL * SEQ];
__device__ bf16 g_Whi[(long)BATCH * SEQ * SEQ], g_Wlo[(long)BATCH * SEQ * SEQ];
__device__ float g_pm[BATCH * ICH * SEQ], g_ps[BATCH * ICH * SEQ];
__device__ float g_gm[BATCH * SEQ], g_gi[BATCH * SEQ];

// ---------------------------------------------------------------------------
// PTX helpers
// ---------------------------------------------------------------------------
__device__ __forceinline__ uint32_t smem_u32(const void* p) {
    uint32_t a;
    asm("{ .reg .u64 t; cvta.to.shared.u64 t, %1; cvt.u32.u64 %0, t; }"
        : "=r"(a) : "l"(p));
    return a;
}
__device__ __forceinline__ void ldm_x4(uint32_t* r, uint32_t addr) {
    asm volatile("ldmatrix.sync.aligned.m8n8.x4.shared.b16 {%0,%1,%2,%3}, [%4];"
        : "=r"(r[0]), "=r"(r[1]), "=r"(r[2]), "=r"(r[3]) : "r"(addr));
}
__device__ __forceinline__ void mma16816(float* c, const uint32_t* a, const uint32_t* b) {
    asm volatile(
        "mma.sync.aligned.m16n8k16.row.col.f32.bf16.bf16.f32 "
        "{%0,%1,%2,%3}, {%4,%5,%6,%7}, {%8,%9}, {%0,%1,%2,%3};"
        : "+f"(c[0]), "+f"(c[1]), "+f"(c[2]), "+f"(c[3])
        : "r"(a[0]), "r"(a[1]), "r"(a[2]), "r"(a[3]), "r"(b[0]), "r"(b[1]));
}
__device__ __forceinline__ void cp16(uint32_t dst, const void* src) {
    asm volatile("cp.async.cg.shared.global [%0], [%1], 16;"
        :: "r"(dst), "l"(src) : "memory");
}
#define CP_COMMIT() asm volatile("cp.async.commit_group;" ::: "memory")
#define CP_WAIT0()  asm volatile("cp.async.wait_group 0;" ::: "memory")
#define CP_WAIT1()  asm volatile("cp.async.wait_group 1;" ::: "memory")

// ---------------------------------------------------------------------------
// cp.async tile load: 128 rows x 32 bf16 hi + 32 bf16 lo -> swizzled tile.
// Chunk c16 (0..7) of row r stored at r*128 + ((c16*16) ^ ((r&7)<<4)).
// ---------------------------------------------------------------------------
__device__ __forceinline__ void cpa_tile(const bf16* __restrict__ hi,
                                         const bf16* __restrict__ lo,
                                         long ld, uint32_t base, int t)
{
    #pragma unroll
    for (int i = 0; i < 2; i++) {
        const int ch = i * 256 + t;      // 0..511
        const int r = ch >> 2, c4 = ch & 3;
        uint32_t dst = base + r * 128 + (uint32_t)((c4 * 16) ^ ((r & 7) << 4));
        cp16(dst, (const char*)(hi + (long)r * ld) + c4 * 16);
    }
    #pragma unroll
    for (int i = 0; i < 2; i++) {
        const int ch = i * 256 + t;
        const int r = ch >> 2, c4 = ch & 3;
        uint32_t dst = base + r * 128 + (uint32_t)(((c4 + 4) * 16) ^ ((r & 7) << 4));
        cp16(dst, (const char*)(lo + (long)r * ld) + c4 * 16);
    }
}

// ===========================================================================
// GEMM on pre-split bf16, 3-term split (hh + hl + lh), 3-stage pipeline.
// A: [M,K] K-major (hi/lo). B: [N,K] K-major (hi/lo). C = alpha * A @ B^T.
// MODE_PROJ  : N=1536 concat; epilogue adds bias (bq/bk/bv) and writes split
//              bf16 into Q/K/V arrays (ld = DMODEL).
// MODE_SCORES: epilogue writes fp32 Cf and per-tile softmax partials pm/ps.
// MODE_AV    : epilogue writes fp32 Cf.
// ===========================================================================
template<int MODE>
__global__ __launch_bounds__(256, 2)
void gemm_ps(const bf16* __restrict__ Ahi, const bf16* __restrict__ Alo,
             const bf16* __restrict__ Bhi, const bf16* __restrict__ Blo,
             float alpha, int M, int N, int K, long sA, long sB, long sC,
             float* __restrict__ Cf,
             float* __restrict__ pm, float* __restrict__ ps,
             const float* __restrict__ bq, const float* __restrict__ bk,
             const float* __restrict__ bv,
             bf16* __restrict__ Qhi, bf16* __restrict__ Qlo,
             bf16* __restrict__ Khi, bf16* __restrict__ Klo,
             bf16* __restrict__ Vhi, bf16* __restrict__ Vlo)
{
    const long za = (long)blockIdx.z * sA;
    const long zb = (long)blockIdx.z * sB;
    const long zc = (long)blockIdx.z * sC;
    const int bm = blockIdx.y * BM;
    const int bn = blockIdx.x * BN;
    const int tid = threadIdx.x;
    const int wid = tid >> 5, lane = tid & 31;
    const int warp_m = wid & 1;
    const int warp_n = wid >> 1;

    extern __shared__ __align__(16) char dynsmem[];
    const uint32_t sbase = smem_u32(dynsmem);

    float acc[4][4][4] = {};

    // ldmatrix lane-address components
    const int a_row = warp_m * 64 + (lane & 15);
    const uint32_t a_k = (uint32_t)(((lane >> 4) * 8) * 2);
    const int b_row = warp_n * 32 + (lane & 7) + ((lane >> 4) * 8);
    const uint32_t b_k = (uint32_t)((((lane >> 3) & 1) * 8) * 2);
    const uint32_t swz = (uint32_t)((lane & 7) << 4);

    const bf16* Ah = Ahi + za + (long)bm * K;
    const bf16* Al = Alo + za + (long)bm * K;
    const bf16* Bh = Bhi + zb + (long)bn * K;
    const bf16* Bl = Blo + zb + (long)bn * K;

    const int nch = K / BKE;

    // Prologue: chunks 0 and 1
    cpa_tile(Ah, Al, K, sbase + 0 * STAGE_B, tid);
    cpa_tile(Bh, Bl, K, sbase + 0 * STAGE_B + TILE_B, tid);
    CP_COMMIT();
    cpa_tile(Ah + BKE, Al + BKE, K, sbase + 1 * STAGE_B, tid);
    cpa_tile(Bh + BKE, Bl + BKE, K, sbase + 1 * STAGE_B + TILE_B, tid);
    CP_COMMIT();

    int stage = 0;
    for (int c = 0; c < nch; c++) {
        if (c + 1 < nch) CP_WAIT1(); else CP_WAIT0();
        __syncthreads();

        // Prefetch chunk c+2 into stage (c+2)%3 (freed at the sync above)
        if (c + 2 < nch) {
            int ns = stage + 2; if (ns >= NSTAGE) ns -= NSTAGE;
            const uint32_t nb = sbase + ns * STAGE_B;
            const int k0 = (c + 2) * BKE;
            cpa_tile(Ah + k0, Al + k0, K, nb, tid);
            cpa_tile(Bh + k0, Bl + k0, K, nb + TILE_B, tid);
            CP_COMMIT();
        }

        const uint32_t uA = sbase + stage * STAGE_B;
        const uint32_t uB = uA + TILE_B;

        #pragma unroll
        for (int ks = 0; ks < 2; ks++) {
            const uint32_t akh = ((a_k + ks * 32) ^ swz);        // A hi
            const uint32_t akl = ((a_k + ks * 32 + 64) ^ swz);   // A lo
            const uint32_t bkh = ((b_k + ks * 32) ^ swz);
            const uint32_t bkl = ((b_k + ks * 32 + 64) ^ swz);
            uint32_t afh[4][4], afl[4][4], bfh[2][4], bfl[2][4];
            #pragma unroll
            for (int mi = 0; mi < 4; mi++)
                ldm_x4(afh[mi], uA + (uint32_t)((a_row + mi * 16) * 128) + akh);
            #pragma unroll
            for (int nb2 = 0; nb2 < 2; nb2++)
                ldm_x4(bfh[nb2], uB + (uint32_t)((b_row + nb2 * 16) * 128) + bkh);
            #pragma unroll
            for (int mi = 0; mi < 4; mi++)
                #pragma unroll
                for (int ni = 0; ni < 4; ni++)
                    mma16816(acc[mi][ni], afh[mi], &bfh[ni >> 1][(ni & 1) * 2]);
            #pragma unroll
            for (int nb2 = 0; nb2 < 2; nb2++)
                ldm_x4(bfl[nb2], uB + (uint32_t)((b_row + nb2 * 16) * 128) + bkl);
            #pragma unroll
            for (int mi = 0; mi < 4; mi++)
                #pragma unroll
                for (int ni = 0; ni < 4; ni++)
                    mma16816(acc[mi][ni], afh[mi], &bfl[ni >> 1][(ni & 1) * 2]);
            #pragma unroll
            for (int mi = 0; mi < 4; mi++)
                ldm_x4(afl[mi], uA + (uint32_t)((a_row + mi * 16) * 128) + akl);
            #pragma unroll
            for (int mi = 0; mi < 4; mi++)
                #pragma unroll
                for (int ni = 0; ni < 4; ni++)
                    mma16816(acc[mi][ni], afl[mi], &bfh[ni >> 1][(ni & 1) * 2]);
        }
        stage = stage + 1; if (stage >= NSTAGE) stage = 0;
    }
    __syncthreads();   // protect smem reuse by epilogue reductions

    // ---------------- Epilogue ----------------
    const int erow = lane >> 2;
    const int ecol = 2 * (lane & 3);

    if (MODE == MODE_PROJ) {
        #pragma unroll
        for (int mi = 0; mi < 4; mi++) {
            #pragma unroll
            for (int ni = 0; ni < 4; ni++) {
                const int col = bn + warp_n * 32 + ni * 8 + ecol;
                const int sel = col >> 9;
                const int nn = col & 511;
                const float* bp = (sel == 0) ? bq : (sel == 1) ? bk : bv;
                bf16* ph = (sel == 0) ? Qhi : (sel == 1) ? Khi : Vhi;
                bf16* pl = (sel == 0) ? Qlo : (sel == 1) ? Klo : Vlo;
                const float bx = bp[nn], by = bp[nn + 1];
                #pragma unroll
                for (int h = 0; h < 2; h++) {
                    const int row = bm + warp_m * 64 + mi * 16 + erow + h * 8;
                    float vx = acc[mi][ni][2 * h + 0] + bx;
                    float vy = acc[mi][ni][2 * h + 1] + by;
                    const long off = (long)row * DMODEL + nn;
                    bf162 hh = __floats2bfloat162_rn(vx, vy);
                    float2 hf = __bfloat1622float2(hh);
                    bf162 ll = __floats2bfloat162_rn(vx - hf.x, vy - hf.y);
                    *(bf162*)(ph + off) = hh;
                    *(bf162*)(pl + off) = ll;
                }
            }
        }
    } else {
        #pragma unroll
        for (int mi = 0; mi < 4; mi++) {
            #pragma unroll
            for (int ni = 0; ni < 4; ni++) {
                const int col = bn + warp_n * 32 + ni * 8 + ecol;
                #pragma unroll
                for (int h = 0; h < 2; h++) {
                    const int row = bm + warp_m * 64 + mi * 16 + erow + h * 8;
                    float2 v;
                    v.x = acc[mi][ni][2 * h + 0] * alpha;
                    v.y = acc[mi][ni][2 * h + 1] * alpha;
                    *(float2*)(Cf + zc + (long)row * N + col) = v;
                }
            }
        }
    }

    if (MODE == MODE_SCORES) {
        // Per-tile column softmax partials over the 128 rows of this CTA.
        float* red_m = (float*)dynsmem;              // [2][128]
        float* red_s = (float*)(dynsmem + 1024);     // [2][128]

        float lm[4][2];
        #pragma unroll
        for (int ni = 0; ni < 4; ni++)
            #pragma unroll
            for (int cc = 0; cc < 2; cc++) {
                float m = -INFINITY;
                #pragma unroll
                for (int mi = 0; mi < 4; mi++)
                    #pragma unroll
                    for (int h = 0; h < 2; h++)
                        m = fmaxf(m, acc[mi][ni][2 * h + cc] * alpha);
                lm[ni][cc] = m;
            }
        #pragma unroll
        for (int off = 4; off < 32; off <<= 1)
            #pragma unroll
            for (int ni = 0; ni < 4; ni++)
                #pragma unroll
                for (int cc = 0; cc < 2; cc++)
                    lm[ni][cc] = fmaxf(lm[ni][cc],
                        __shfl_xor_sync(0xffffffffu, lm[ni][cc], off));
        if (lane < 4) {
            #pragma unroll
            for (int ni = 0; ni < 4; ni++)
                #pragma unroll
                for (int cc = 0; cc < 2; cc++)
                    red_m[warp_m * 128 + warp_n * 32 + ni * 8 + 2 * lane + cc] = lm[ni][cc];
        }
        __syncthreads();

        float cmax[4][2], lsum[4][2];
        #pragma unroll
        for (int ni = 0; ni < 4; ni++)
            #pragma unroll
            for (int cc = 0; cc < 2; cc++) {
                const int cl = warp_n * 32 + ni * 8 + ecol + cc;
                cmax[ni][cc] = fmaxf(red_m[cl], red_m[128 + cl]);
                float s = 0.f;
                #pragma unroll
                for (int mi = 0; mi < 4; mi++)
                    #pragma unroll
                    for (int h = 0; h < 2; h++)
                        s += __expf(acc[mi][ni][2 * h + cc] * alpha - cmax[ni][cc]);
                lsum[ni][cc] = s;
            }
        #pragma unroll
        for (int off = 4; off < 32; off <<= 1)
            #pragma unroll
            for (int ni = 0; ni < 4; ni++)
                #pragma unroll
                for (int cc = 0; cc < 2; cc++)
                    lsum[ni][cc] += __shfl_xor_sync(0xffffffffu, lsum[ni][cc], off);
        if (lane < 4) {
            #pragma unroll
            for (int ni = 0; ni < 4; ni++)
                #pragma unroll
                for (int cc = 0; cc < 2; cc++)
                    red_s[warp_m * 128 + warp_n * 32 + ni * 8 + 2 * lane + cc] = lsum[ni][cc];
        }
        __syncthreads();

        if (warp_m == 0 && lane < 4) {
            const long pbase = ((long)blockIdx.z * ICH + blockIdx.y) * SEQ + bn;
            #pragma unroll
            for (int ni = 0; ni < 4; ni++)
                #pragma unroll
                for (int cc = 0; cc < 2; cc++) {
                    const int cl = warp_n * 32 + ni * 8 + 2 * lane + cc;
                    pm[pbase + cl] = cmax[ni][cc];
                    ps[pbase + cl] = red_s[cl] + red_s[128 + cl];
                }
        }
    }
}

// ---------------------------------------------------------------------------
// fp32 -> hi/lo bf16 elementwise (vectorized by 4)
// ---------------------------------------------------------------------------
__global__ void split_fp32(const float* __restrict__ src,
                           bf16* __restrict__ hi, bf16* __restrict__ lo, long n4)
{
    const long i = (long)blockIdx.x * blockDim.x + threadIdx.x;
    if (i >= n4) return;
    float4 a = ((const float4*)src)[i];
    bf162 h0 = __floats2bfloat162_rn(a.x, a.y);
    bf162 h1 = __floats2bfloat162_rn(a.z, a.w);
    float2 f0 = __bfloat1622float2(h0);
    float2 f1 = __bfloat1622float2(h1);
    bf162 l0 = __floats2bfloat162_rn(a.x - f0.x, a.y - f0.y);
    bf162 l1 = __floats2bfloat162_rn(a.z - f1.x, a.w - f1.y);
    ((bf162*)hi)[2 * i] = h0; ((bf162*)hi)[2 * i + 1] = h1;
    ((bf162*)lo)[2 * i] = l0; ((bf162*)lo)[2 * i + 1] = l1;
}

// ---------------------------------------------------------------------------
// Transpose + split: W fp32 [K=512][N=512] -> Wt split bf16 [n][k]
// ---------------------------------------------------------------------------
__global__ void transpose_split_w(const float* __restrict__ W,
                                  bf16* __restrict__ Thi, bf16* __restrict__ Tlo)
{
    __shared__ float tile[32][33];
    const int k0 = blockIdx.y * 32, n0 = blockIdx.x * 32;
    const int tx = threadIdx.x, ty = threadIdx.y;
    #pragma unroll
    for (int yy = 0; yy < 32; yy += 8)
        tile[ty + yy][tx] = W[(long)(k0 + ty + yy) * DMODEL + n0 + tx];
    __syncthreads();
    #pragma unroll
    for (int yy = 0; yy < 32; yy += 8) {
        float v = tile[tx][ty + yy];
        bf16 h = __float2bfloat16_rn(v);
        bf16 l = __float2bfloat16_rn(v - __bfloat162float(h));
        Thi[(long)(n0 + ty + yy) * DMODEL + k0 + tx] = h;
        Tlo[(long)(n0 + ty + yy) * DMODEL + k0 + tx] = l;
    }
}

// ---------------------------------------------------------------------------
// Transpose split-bf16 V [b*N + n][e] -> Vt [b][e][n]
// ---------------------------------------------------------------------------
__global__ void transpose_v(const bf16* __restrict__ Vhi, const bf16* __restrict__ Vlo,
                            bf16* __restrict__ Thi, bf16* __restrict__ Tlo)
{
    __shared__ bf16 th[32][33], tl[32][33];
    const long b = blockIdx.z;
    const int e0 = blockIdx.x * 32, n0 = blockIdx.y * 32;
    const int tx = threadIdx.x, ty = threadIdx.y;
    #pragma unroll
    for (int yy = 0; yy < 32; yy += 8) {
        const long src = (b * SEQ + n0 + ty + yy) * DMODEL + e0 + tx;
        th[ty + yy][tx] = Vhi[src];
        tl[ty + yy][tx] = Vlo[src];
    }
    __syncthreads();
    #pragma unroll
    for (int yy = 0; yy < 32; yy += 8) {
        const long dst = b * DMODEL * SEQ + (long)(e0 + ty + yy) * SEQ + n0 + tx;
        Thi[dst] = th[tx][ty + yy];
        Tlo[dst] = tl[tx][ty + yy];
    }
}

// ---------------------------------------------------------------------------
// Softmax combine + normalize (pass1 partials come from the scores epilogue)
// ---------------------------------------------------------------------------
__global__ void sm_pass2(const float* __restrict__ pm, const float* __restrict__ ps,
                         float* __restrict__ gm, float* __restrict__ gi)
{
    const int j = blockIdx.x * blockDim.x + threadIdx.x;
    const long b = blockIdx.y;
    float m = -INFINITY;
    #pragma unroll
    for (int ic = 0; ic < ICH; ic++)
        m = fmaxf(m, pm[(b * ICH + ic) * SEQ + j]);
    float s = 0.0f;
    #pragma unroll
    for (int ic = 0; ic < ICH; ic++)
        s += ps[(b * ICH + ic) * SEQ + j] * __expf(pm[(b * ICH + ic) * SEQ + j] - m);
    gm[b * SEQ + j] = m;
    gi[b * SEQ + j] = 1.0f / s;
}

__global__ void sm_pass3(float* __restrict__ S,
                         const float* __restrict__ gm, const float* __restrict__ gi,
                         bf16* __restrict__ whi, bf16* __restrict__ wlo)
{
    const int j4 = (blockIdx.x * blockDim.x + threadIdx.x) * 4;
    const int i = blockIdx.y;
    const long b = blockIdx.z;
    const long off = b * (long)SEQ * SEQ + (long)i * SEQ + j4;
    float4 x = *(const float4*)(S + off);
    float4 m = *(const float4*)(gm + b * SEQ + j4);
    float4 v = *(const float4*)(gi + b * SEQ + j4);
    float4 w;
    w.x = __expf(x.x - m.x) * v.x;
    w.y = __expf(x.y - m.y) * v.y;
    w.z = __expf(x.z - m.z) * v.z;
    w.w = __expf(x.w - m.w) * v.w;
    *(float4*)(S + off) = w;
    bf162 h0 = __floats2bfloat162_rn(w.x, w.y);
    bf162 h1 = __floats2bfloat162_rn(w.z, w.w);
    float2 f0 = __bfloat1622float2(h0);
    float2 f1 = __bfloat1622float2(h1);
    bf162 l0 = __floats2bfloat162_rn(w.x - f0.x, w.y - f0.y);
    bf162 l1 = __floats2bfloat162_rn(w.z - f1.x, w.w - f1.y);
    *(bf162*)(whi + off) = h0; *(bf162*)(whi + off + 2) = h1;
    *(bf162*)(wlo + off) = l0; *(bf162*)(wlo + off + 2) = l1;
}

// ---------------------------------------------------------------------------
// kernel_launch
// ---------------------------------------------------------------------------
extern "C" void kernel_launch(void* const* d_in, const int* in_sizes, int n_in,
                              void* d_out, int out_size)
{
    const float* x  = (const float*)d_in[0];
    const float* Wq = (const float*)d_in[1];
    const float* bq = (const float*)d_in[2];
    const float* Wk = (const float*)d_in[3];
    const float* bk = (const float*)d_in[4];
    const float* Wv = (const float*)d_in[5];
    const float* bv = (const float*)d_in[6];

    float* out     = (float*)d_out;
    float* weights = out + (long)BATCH * SEQ * DMODEL;

    bf16 *xhi, *xlo, *Wthi, *Wtlo, *Qhi, *Qlo, *Khi, *Klo, *Vhi, *Vlo;
    bf16 *Vthi, *Vtlo, *Whi, *Wlo;
    float *pm, *ps, *gm, *gi;
    cudaGetSymbolAddress((void**)&xhi, g_xhi);   cudaGetSymbolAddress((void**)&xlo, g_xlo);
    cudaGetSymbolAddress((void**)&Wthi, g_Wthi); cudaGetSymbolAddress((void**)&Wtlo, g_Wtlo);
    cudaGetSymbolAddress((void**)&Qhi, g_Qhi);   cudaGetSymbolAddress((void**)&Qlo, g_Qlo);
    cudaGetSymbolAddress((void**)&Khi, g_Khi);   cudaGetSymbolAddress((void**)&Klo, g_Klo);
    cudaGetSymbolAddress((void**)&Vhi, g_Vhi);   cudaGetSymbolAddress((void**)&Vlo, g_Vlo);
    cudaGetSymbolAddress((void**)&Vthi, g_Vthi); cudaGetSymbolAddress((void**)&Vtlo, g_Vtlo);
    cudaGetSymbolAddress((void**)&Whi, g_Whi);   cudaGetSymbolAddress((void**)&Wlo, g_Wlo);
    cudaGetSymbolAddress((void**)&pm, g_pm);     cudaGetSymbolAddress((void**)&ps, g_ps);
    cudaGetSymbolAddress((void**)&gm, g_gm);     cudaGetSymbolAddress((void**)&gi, g_gi);

    static bool attr_set = false;
    if (!attr_set) {
        cudaFuncSetAttribute(gemm_ps<MODE_PROJ>,
                             cudaFuncAttributeMaxDynamicSharedMemorySize, DYN_SMEM);
        cudaFuncSetAttribute(gemm_ps<MODE_SCORES>,
                             cudaFuncAttributeMaxDynamicSharedMemorySize, DYN_SMEM);
        cudaFuncSetAttribute(gemm_ps<MODE_AV>,
                             cudaFuncAttributeMaxDynamicSharedMemorySize, DYN_SMEM);
        attr_set = true;
    }

    const dim3 blk(256);
    const long MD = (long)BATCH * SEQ * DMODEL;

    // 0) split inputs
    split_fp32<<<(unsigned)((MD / 4 + 255) / 256), blk>>>(x, xhi, xlo, MD / 4);
    {
        dim3 g(16, 16), b(32, 8);
        transpose_split_w<<<g, b>>>(Wq, Wthi + 0 * DMODEL * DMODEL, Wtlo + 0 * DMODEL * DMODEL);
        transpose_split_w<<<g, b>>>(Wk, Wthi + 1 * DMODEL * DMODEL, Wtlo + 1 * DMODEL * DMODEL);
        transpose_split_w<<<g, b>>>(Wv, Wthi + 2 * DMODEL * DMODEL, Wtlo + 2 * DMODEL * DMODEL);
    }

    // 1) fused QKV projection: [16384, 1536] = x @ [Wq|Wk|Wv]^T, split outputs
    {
        dim3 grid(3 * DMODEL / BN, (BATCH * SEQ) / BM, 1);
        gemm_ps<MODE_PROJ><<<grid, blk, DYN_SMEM>>>(xhi, xlo, Wthi, Wtlo,
            1.0f, BATCH * SEQ, 3 * DMODEL, DMODEL, 0, 0, 0,
            nullptr, nullptr, nullptr, bq, bk, bv,
            Qhi, Qlo, Khi, Klo, Vhi, Vlo);
    }

    // 1b) V -> Vt (per batch [e][n])
    {
        dim3 g(DMODEL / 32, SEQ / 32, BATCH), b(32, 8);
        transpose_v<<<g, b>>>(Vhi, Vlo, Vthi, Vtlo);
    }

    // 2) scores = scale * Q @ K^T -> weights (fp32) + softmax partials
    {
        const float scale = 1.0f / sqrtf((float)DMODEL);
        dim3 grid(SEQ / BN, SEQ / BM, BATCH);
        gemm_ps<MODE_SCORES><<<grid, blk, DYN_SMEM>>>(Qhi, Qlo, Khi, Klo,
            scale, SEQ, SEQ, DMODEL,
            (long)SEQ * DMODEL, (long)SEQ * DMODEL, (long)SEQ * SEQ,
            weights, pm, ps, nullptr, nullptr, nullptr,
            nullptr, nullptr, nullptr, nullptr, nullptr, nullptr);
    }

    // 3) softmax combine + normalize (pass3 also emits split bf16 weights)
    {
        dim3 g2(SEQ / 256, BATCH);
        sm_pass2<<<g2, blk>>>(pm, ps, gm, gi);
        dim3 g3(SEQ / (256 * 4), SEQ, BATCH);
        sm_pass3<<<g3, blk>>>(weights, gm, gi, Whi, Wlo);
    }

    // 4) out = weights @ V  (B = Vt [e][j], K-major over j)
    {
        dim3 grid(DMODEL / BN, SEQ / BM, BATCH);
        gemm_ps<MODE_AV><<<grid, blk, DYN_SMEM>>>(Whi, Wlo, Vthi, Vtlo,
            1.0f, SEQ, DMODEL, SEQ,
            (long)SEQ * SEQ, (long)DMODEL * SEQ, (long)SEQ * DMODEL,
            out, nullptr, nullptr, nullptr, nullptr, nullptr,
            nullptr, nullptr, nullptr, nullptr, nullptr, nullptr);
    }
}